// round 15
// baseline (speedup 1.0000x reference)
#include <cuda_runtime.h>
#include <cuda_bf16.h>
#include <math.h>
#include <stdint.h>

// Problem constants
#define BATCH 2
#define SEQ   2048
#define DIM   768
#define NH    12
#define DH    64
#define ROPE_DIM 60
#define HALF  10
#define NT    (SEQ / 64)   // 32 key tiles of 64

// ---------------- scratch (static device arrays; no allocation) -------------
__device__ float g_qkv[BATCH * SEQ * 3 * DIM];
__device__ float g_q[BATCH * NH * SEQ * DH];
__device__ float g_k[BATCH * NH * SEQ * DH];
__device__ float g_v[BATCH * NH * SEQ * DH];
__device__ float g_att[BATCH * SEQ * DIM];

// ---------------- cp.async helpers ------------------------------------------
__device__ __forceinline__ void cp_async16(void* smem_dst, const void* gmem_src) {
    unsigned s = (unsigned)__cvta_generic_to_shared(smem_dst);
    asm volatile("cp.async.cg.shared.global [%0], [%1], 16;" :: "r"(s), "l"(gmem_src));
}
__device__ __forceinline__ void cp_commit() {
    asm volatile("cp.async.commit_group;");
}
template<int N>
__device__ __forceinline__ void cp_wait() {
    asm volatile("cp.async.wait_group %0;" :: "n"(N));
}

// ---------------- mma.sync tf32 helpers (sm_80+, valid on plain sm_100) -----
__device__ __forceinline__ uint32_t f2tf32(float x) {
    uint32_t r;
    asm("cvt.rna.tf32.f32 %0, %1;" : "=r"(r) : "f"(x));
    return r;
}
__device__ __forceinline__ void mma_tf32(float* d, const uint32_t* a, const uint32_t* b) {
    asm volatile(
        "mma.sync.aligned.m16n8k8.row.col.f32.tf32.tf32.f32 "
        "{%0,%1,%2,%3}, {%4,%5,%6,%7}, {%8,%9}, {%0,%1,%2,%3};"
        : "+f"(d[0]), "+f"(d[1]), "+f"(d[2]), "+f"(d[3])
        : "r"(a[0]), "r"(a[1]), "r"(a[2]), "r"(a[3]), "r"(b[0]), "r"(b[1]));
}

// =====================================================================
// GEMM via mma.sync tf32 (R13-certified math; + minctas=2 for occupancy).
// =====================================================================
#define BMM 128
#define BNN 128
#define BKK 32
#define ASTR 36
#define GT_BUF (2 * BMM * ASTR)
#define GT_SMEM (2 * GT_BUF * 4)

__global__ __launch_bounds__(256, 2)
void gemm_mma_kernel(const float* __restrict__ A, const float* __restrict__ Bw,
                     const float* __restrict__ bias, float* __restrict__ C,
                     int M, int Nn, int K)
{
    extern __shared__ float smg[];
    const int tid = threadIdx.x;
    const int lane = tid & 31, wid = tid >> 5;
    const int wr = wid >> 2, wc = wid & 3;
    const int gid = lane >> 2, tg = lane & 3;
    const int mBase = blockIdx.y * BMM;
    const int nBase = blockIdx.x * BNN;
    const int nTiles = K / BKK;

    float d[4][4][4];
#pragma unroll
    for (int mf = 0; mf < 4; ++mf)
#pragma unroll
        for (int nf = 0; nf < 4; ++nf)
#pragma unroll
            for (int e = 0; e < 4; ++e) d[mf][nf][e] = 0.f;

    auto load_tile = [&](int t, int buf) {
        const float* At = A + (size_t)mBase * K + t * BKK;
        const float* Bt = Bw + (size_t)nBase * K + t * BKK;
        float* as = smg + buf * GT_BUF;
        float* bs = as + BMM * ASTR;
#pragma unroll
        for (int e = 0; e < 8; ++e) {
            int idx = tid + e * 256;
            int r = (idx >> 3) & 127;
            int c = idx & 7;
            if (idx < 1024)
                cp_async16(&as[r * ASTR + c * 4], &At[(size_t)r * K + c * 4]);
            else
                cp_async16(&bs[r * ASTR + c * 4], &Bt[(size_t)r * K + c * 4]);
        }
        cp_commit();
    };

    load_tile(0, 0);
    cp_wait<0>();
    __syncthreads();

    for (int t = 0; t < nTiles; ++t) {
        int cur = t & 1;
        if (t + 1 < nTiles) load_tile(t + 1, cur ^ 1);

        const float* as = smg + cur * GT_BUF;
        const float* bs = as + BMM * ASTR;

#pragma unroll
        for (int ks = 0; ks < BKK / 8; ++ks) {
            int k0 = ks * 8;
            uint32_t af[4][4];
#pragma unroll
            for (int mf = 0; mf < 4; ++mf) {
                int mr = wr * 64 + mf * 16 + gid;
                af[mf][0] = f2tf32(as[mr * ASTR + k0 + tg]);
                af[mf][1] = f2tf32(as[(mr + 8) * ASTR + k0 + tg]);
                af[mf][2] = f2tf32(as[mr * ASTR + k0 + tg + 4]);
                af[mf][3] = f2tf32(as[(mr + 8) * ASTR + k0 + tg + 4]);
            }
            uint32_t bf[4][2];
#pragma unroll
            for (int nf = 0; nf < 4; ++nf) {
                int nc = wc * 32 + nf * 8 + gid;
                bf[nf][0] = f2tf32(bs[nc * ASTR + k0 + tg]);
                bf[nf][1] = f2tf32(bs[nc * ASTR + k0 + tg + 4]);
            }
#pragma unroll
            for (int mf = 0; mf < 4; ++mf)
#pragma unroll
                for (int nf = 0; nf < 4; ++nf)
                    mma_tf32(d[mf][nf], af[mf], bf[nf]);
        }

        if (t + 1 < nTiles) cp_wait<0>();
        __syncthreads();
    }

#pragma unroll
    for (int mf = 0; mf < 4; ++mf) {
#pragma unroll
        for (int nf = 0; nf < 4; ++nf) {
            int row = mBase + wr * 64 + mf * 16 + gid;
            int col = nBase + wc * 32 + nf * 8 + 2 * tg;
            float b0 = bias ? bias[col]     : 0.f;
            float b1 = bias ? bias[col + 1] : 0.f;
            float2 v0 = {d[mf][nf][0] + b0, d[mf][nf][1] + b1};
            float2 v1 = {d[mf][nf][2] + b0, d[mf][nf][3] + b1};
            *(float2*)&C[(size_t)row * Nn + col] = v0;
            *(float2*)&C[(size_t)(row + 8) * Nn + col] = v1;
        }
    }
}

// =====================================================================
// Warp-parallel rmsnorm + rope + split (unchanged — certified R8/R9).
// =====================================================================
__global__ void norm_rope_warp(const float* __restrict__ pos,
                               const float* __restrict__ qn_w,
                               const float* __restrict__ kn_w)
{
    int gw = (blockIdx.x * blockDim.x + threadIdx.x) >> 5;
    int t  = threadIdx.x & 31;
    if (gw >= BATCH * SEQ * NH) return;
    int h   = gw % NH;
    int tok = gw / NH;
    int b = tok / SEQ, n = tok % SEQ;

    const size_t base = (size_t)tok * (3 * DIM) + h * DH + 2 * t;
    float2 qv = *(const float2*)&g_qkv[base];
    float2 kv = *(const float2*)&g_qkv[base + DIM];
    float2 vv = *(const float2*)&g_qkv[base + 2 * DIM];

    float sq = qv.x * qv.x + qv.y * qv.y;
    float sk = kv.x * kv.x + kv.y * kv.y;
#pragma unroll
    for (int o = 16; o; o >>= 1) {
        sq += __shfl_xor_sync(0xffffffffu, sq, o);
        sk += __shfl_xor_sync(0xffffffffu, sk, o);
    }
    float rq = rsqrtf(sq * (1.0f / DH) + 1e-6f);
    float rk = rsqrtf(sk * (1.0f / DH) + 1e-6f);
    qv.x *= rq * qn_w[2 * t]; qv.y *= rq * qn_w[2 * t + 1];
    kv.x *= rk * kn_w[2 * t]; kv.y *= rk * kn_w[2 * t + 1];

    if (t < ROPE_DIM / 2) {
        int axis = t / HALF;
        int j = t - axis * HALF;
        float freq = powf(10000.0f, -(float)j / (float)HALF);
        float ang = pos[(size_t)tok * 3 + axis] * freq;
        float c = cosf(ang), s = sinf(ang);
        float qe = qv.x * c - qv.y * s, qo = qv.x * s + qv.y * c;
        qv.x = qe; qv.y = qo;
        float ke = kv.x * c - kv.y * s, ko = kv.x * s + kv.y * c;
        kv.x = ke; kv.y = ko;
    }

    const size_t ob = ((size_t)(b * NH + h) * SEQ + n) * DH + 2 * t;
    *(float2*)&g_q[ob] = qv;
    *(float2*)&g_k[ob] = kv;
    *(float2*)&g_v[ob] = vv;
}

// =====================================================================
// Flash attention v6 = certified v5 with q-tile 64 (was 128):
//   smem 104448 B -> 2 CTA/SM; accumulators halved -> regs < 128.
// 8 warps, 2x4 grid: warp (wr,wc) -> rows [wr*32+mf*16) x cols [wc*16).
// All fragment mappings identical to v5; only mf range (2) and row
// bases (wr*32) change. Pipeline & P-rounding unchanged.
// =====================================================================
#define SST 68
#define A6_SMEM (384 * SST * 4)     // (64+64*2+64*2+64) rows = 104448 B
#define RPX 17

__global__ __launch_bounds__(256, 2)
void attn6_kernel()
{
    extern __shared__ float sm[];
    float* Qs  = sm;                  // [64][SST] tf32 bits
    float* Ks0 = Qs  + 64 * SST;      // [64][SST] fp32
    float* Ks1 = Ks0 + 64 * SST;
    float* Vt0 = Ks1 + 64 * SST;      // [64][SST] tf32 bits (V^T)
    float* Vt1 = Vt0 + 64 * SST;
    float* Ss  = Vt1 + 64 * SST;      // [64][SST] tf32 bits (P)

    const int tid = threadIdx.x;
    const int lane = tid & 31, wid = tid >> 5;
    const int wr = wid >> 2, wc = wid & 3;
    const int gid = lane >> 2, tg = lane & 3;
    const int bh = blockIdx.y;
    const int b  = bh / NH, h = bh % NH;
    const int n0 = blockIdx.x * 64;

    const float* Qg = g_q + ((size_t)bh * SEQ + n0) * DH;
    const float* Kg = g_k + (size_t)bh * SEQ * DH;
    const float* Vg = g_v + (size_t)bh * SEQ * DH;

    // ---- Q tile: load, convert to tf32 bits, natural [q][d] ----
#pragma unroll
    for (int e = 0; e < 16; ++e) {
        int idx = tid + e * 256;          // 0..4095
        int q = idx >> 6, dd = idx & 63;
        Qs[q * SST + dd] = __uint_as_float(f2tf32(Qg[(size_t)q * DH + dd]));
    }

    auto load_k = [&](const float* src, float* dst) {
#pragma unroll
        for (int e = 0; e < 4; ++e) {
            int fidx = tid + e * 256;
            int r = fidx >> 4, c4 = (fidx & 15) * 4;
            cp_async16(&dst[r * SST + c4], &src[(size_t)r * DH + c4]);
        }
        cp_commit();
    };
    const int lrv = tid & 63;             // k row
    const int ldv = tid >> 6;             // d base 0..3

    // ---- preload tile 0 ----
    load_k(Kg, Ks0);
#pragma unroll
    for (int e = 0; e < 16; ++e) {
        uint32_t v = f2tf32(Vg[(size_t)lrv * DH + ldv + e * 4]);
        Vt0[(ldv + e * 4) * SST + lrv] = __uint_as_float(v);
    }
    cp_wait<0>();
    __syncthreads();     // (A) for kt=0

    float o[2][2][4];
    float lsA[2], lsB[2];
#pragma unroll
    for (int mf = 0; mf < 2; ++mf) {
        lsA[mf] = 0.f; lsB[mf] = 0.f;
#pragma unroll
        for (int nf = 0; nf < 2; ++nf)
#pragma unroll
            for (int e = 0; e < 4; ++e) o[mf][nf][e] = 0.f;
    }

    for (int kt = 0; kt < NT; ++kt) {
        float* Ksc = (kt & 1) ? Ks1 : Ks0;
        float* Vtc = (kt & 1) ? Vt1 : Vt0;
        float* Ksn = (kt & 1) ? Ks0 : Ks1;
        float* Vtn = (kt & 1) ? Vt0 : Vt1;

        // ---- prefetch next tile (safe: past sync A) ----
        uint32_t vreg[16];
        if (kt + 1 < NT) {
            const float* Kgn = Kg + (size_t)(kt + 1) * 64 * DH;
            const float* Vgn = Vg + (size_t)(kt + 1) * 64 * DH;
            load_k(Kgn, Ksn);
#pragma unroll
            for (int e = 0; e < 16; ++e)
                vreg[e] = f2tf32(Vgn[(size_t)lrv * DH + ldv + e * 4]);
        }

        // ---- S = Q K^T (tf32 mma) ----
        float s[2][2][4];
#pragma unroll
        for (int mf = 0; mf < 2; ++mf)
#pragma unroll
            for (int nf = 0; nf < 2; ++nf)
#pragma unroll
                for (int e = 0; e < 4; ++e) s[mf][nf][e] = 0.f;

#pragma unroll
        for (int ds = 0; ds < 8; ++ds) {
            int d0 = ds * 8;
            uint32_t af[2][4];
#pragma unroll
            for (int mf = 0; mf < 2; ++mf) {
                int mr = wr * 32 + mf * 16 + gid;
                af[mf][0] = __float_as_uint(Qs[mr * SST + d0 + tg]);
                af[mf][1] = __float_as_uint(Qs[(mr + 8) * SST + d0 + tg]);
                af[mf][2] = __float_as_uint(Qs[mr * SST + d0 + tg + 4]);
                af[mf][3] = __float_as_uint(Qs[(mr + 8) * SST + d0 + tg + 4]);
            }
            uint32_t bf[2][2];
#pragma unroll
            for (int nf = 0; nf < 2; ++nf) {
                int kc = wc * 16 + nf * 8 + gid;
                bf[nf][0] = f2tf32(Ksc[kc * SST + d0 + tg]);
                bf[nf][1] = f2tf32(Ksc[kc * SST + d0 + tg + 4]);
            }
#pragma unroll
            for (int mf = 0; mf < 2; ++mf)
#pragma unroll
                for (int nf = 0; nf < 2; ++nf)
                    mma_tf32(s[mf][nf], af[mf], bf[nf]);
        }

        // ---- P = exp(S/8), RNA-round to tf32, sum rounded, store ----
#pragma unroll
        for (int mf = 0; mf < 2; ++mf) {
            int r0 = wr * 32 + mf * 16 + gid;
#pragma unroll
            for (int nf = 0; nf < 2; ++nf) {
                int col = wc * 16 + nf * 8 + 2 * tg;
                float p0 = __uint_as_float(f2tf32(__expf(s[mf][nf][0] * 0.125f)));
                float p1 = __uint_as_float(f2tf32(__expf(s[mf][nf][1] * 0.125f)));
                float p2 = __uint_as_float(f2tf32(__expf(s[mf][nf][2] * 0.125f)));
                float p3 = __uint_as_float(f2tf32(__expf(s[mf][nf][3] * 0.125f)));
                lsA[mf] += p0 + p1;
                lsB[mf] += p2 + p3;
                *(float2*)&Ss[r0 * SST + col] = make_float2(p0, p1);
                *(float2*)&Ss[(r0 + 8) * SST + col] = make_float2(p2, p3);
            }
        }
        __syncthreads();   // (B) P visible to all warps

        // ---- O += P V (tf32 mma; A=P from Ss, B=V^T from Vtc) ----
#pragma unroll
        for (int ks = 0; ks < 8; ++ks) {
            int kk0 = ks * 8;
            uint32_t af[2][4];
#pragma unroll
            for (int mf = 0; mf < 2; ++mf) {
                int mr = wr * 32 + mf * 16 + gid;
                af[mf][0] = __float_as_uint(Ss[mr * SST + kk0 + tg]);
                af[mf][1] = __float_as_uint(Ss[(mr + 8) * SST + kk0 + tg]);
                af[mf][2] = __float_as_uint(Ss[mr * SST + kk0 + tg + 4]);
                af[mf][3] = __float_as_uint(Ss[(mr + 8) * SST + kk0 + tg + 4]);
            }
            uint32_t bf[2][2];
#pragma unroll
            for (int nf = 0; nf < 2; ++nf) {
                int dc = wc * 16 + nf * 8 + gid;
                bf[nf][0] = __float_as_uint(Vtc[dc * SST + kk0 + tg]);
                bf[nf][1] = __float_as_uint(Vtc[dc * SST + kk0 + tg + 4]);
            }
#pragma unroll
            for (int mf = 0; mf < 2; ++mf)
#pragma unroll
                for (int nf = 0; nf < 2; ++nf)
                    mma_tf32(o[mf][nf], af[mf], bf[nf]);
        }

        // ---- stage next V^T -> other buffer (readers done pre-syncA) ----
        if (kt + 1 < NT) {
#pragma unroll
            for (int e = 0; e < 16; ++e)
                Vtn[(ldv + e * 4) * SST + lrv] = __uint_as_float(vreg[e]);
        }

        cp_wait<0>();
        __syncthreads();   // (A) next buffers ready; Ss free
    }

    // ---- final row-sum reduction (reuse Ks0 as scratch [64][RPX]) ----
    float* red = Ks0;
#pragma unroll
    for (int mf = 0; mf < 2; ++mf) {
        int r0 = wr * 32 + mf * 16 + gid;
        red[r0 * RPX + wc * 4 + tg] = lsA[mf];
        red[(r0 + 8) * RPX + wc * 4 + tg] = lsB[mf];
    }
    __syncthreads();

#pragma unroll
    for (int mf = 0; mf < 2; ++mf) {
        int r0 = wr * 32 + mf * 16 + gid;
        float lA = 0.f, lB = 0.f;
#pragma unroll
        for (int t = 0; t < 16; ++t) {
            lA += red[r0 * RPX + t];
            lB += red[(r0 + 8) * RPX + t];
        }
        float invA = 1.0f / lA, invB = 1.0f / lB;
#pragma unroll
        for (int nf = 0; nf < 2; ++nf) {
            int dcol = wc * 16 + nf * 8 + 2 * tg;
            size_t offA = ((size_t)(b * SEQ + n0 + r0) * NH + h) * DH + dcol;
            size_t offB = ((size_t)(b * SEQ + n0 + r0 + 8) * NH + h) * DH + dcol;
            *(float2*)&g_att[offA] = make_float2(o[mf][nf][0] * invA,
                                                 o[mf][nf][1] * invA);
            *(float2*)&g_att[offB] = make_float2(o[mf][nf][2] * invB,
                                                 o[mf][nf][3] * invB);
        }
    }
}

// =====================================================================
// host launcher
// =====================================================================
extern "C" void kernel_launch(void* const* d_in, const int* in_sizes, int n_in,
                              void* d_out, int out_size)
{
    const float *x = 0, *pos = 0, *qkv_w = 0, *proj_w = 0, *proj_b = 0;
    const float *qn_w = 0, *kn_w = 0;
    for (int i = 0; i < n_in; ++i) {
        int s = in_sizes[i];
        const float* p = (const float*)d_in[i];
        if      (s == BATCH * SEQ * DIM)  x = p;
        else if (s == BATCH * SEQ * 3)    pos = p;
        else if (s == 3 * DIM * DIM)      qkv_w = p;
        else if (s == DIM * DIM)          proj_w = p;
        else if (s == DIM)                proj_b = p;
        else if (s == DH) { if (!qn_w) qn_w = p; else kn_w = p; }
    }
    float* out = (float*)d_out;

    float *qkv, *att;
    cudaGetSymbolAddress((void**)&qkv, g_qkv);
    cudaGetSymbolAddress((void**)&att, g_att);

    cudaFuncSetAttribute(gemm_mma_kernel, cudaFuncAttributeMaxDynamicSharedMemorySize,
                         GT_SMEM);
    cudaFuncSetAttribute(attn6_kernel, cudaFuncAttributeMaxDynamicSharedMemorySize,
                         A6_SMEM);

    // 1) qkv = x @ qkv_w^T  (tf32 mma.sync)
    gemm_mma_kernel<<<dim3(3 * DIM / BNN, BATCH * SEQ / BMM), 256, GT_SMEM>>>(
        x, qkv_w, nullptr, qkv, BATCH * SEQ, 3 * DIM, DIM);

    // 2) rmsnorm + rope + split
    {
        int totalWarps = BATCH * SEQ * NH;
        int threads = 256;
        int blocks = (totalWarps * 32 + threads - 1) / threads;
        norm_rope_warp<<<blocks, threads>>>(pos, qn_w, kn_w);
    }

    // 3) flash attention v6 (tf32 mma.sync, 2 CTA/SM)
    attn6_kernel<<<dim3(SEQ / 64, BATCH * NH), 256, A6_SMEM>>>();

    // 4) out = att @ proj_w^T + proj_b  (tf32 mma.sync)
    gemm_mma_kernel<<<dim3(DIM / BNN, BATCH * SEQ / BMM), 256, GT_SMEM>>>(
        att, proj_w, proj_b, out, BATCH * SEQ, DIM, DIM);
}

// round 16
// speedup vs baseline: 1.3327x; 1.3327x over previous
#include <cuda_runtime.h>
#include <cuda_bf16.h>
#include <math.h>
#include <stdint.h>

// Problem constants
#define BATCH 2
#define SEQ   2048
#define DIM   768
#define NH    12
#define DH    64
#define ROPE_DIM 60
#define HALF  10
#define NT    (SEQ / 64)   // 32 key tiles of 64

// ---------------- scratch (static device arrays; no allocation) -------------
__device__ float g_qkv[BATCH * SEQ * 3 * DIM];
__device__ float g_q[BATCH * NH * SEQ * DH];   // tf32-rounded at write
__device__ float g_k[BATCH * NH * SEQ * DH];   // tf32-rounded at write
__device__ float g_v[BATCH * NH * SEQ * DH];   // tf32-rounded at write
__device__ float g_att[BATCH * SEQ * DIM];

// ---------------- cp.async helpers ------------------------------------------
__device__ __forceinline__ void cp_async16(void* smem_dst, const void* gmem_src) {
    unsigned s = (unsigned)__cvta_generic_to_shared(smem_dst);
    asm volatile("cp.async.cg.shared.global [%0], [%1], 16;" :: "r"(s), "l"(gmem_src));
}
__device__ __forceinline__ void cp_commit() {
    asm volatile("cp.async.commit_group;");
}
template<int N>
__device__ __forceinline__ void cp_wait() {
    asm volatile("cp.async.wait_group %0;" :: "n"(N));
}

// ---------------- mma.sync tf32 helpers (sm_80+, valid on plain sm_100) -----
__device__ __forceinline__ uint32_t f2tf32(float x) {
    uint32_t r;
    asm("cvt.rna.tf32.f32 %0, %1;" : "=r"(r) : "f"(x));
    return r;
}
__device__ __forceinline__ void mma_tf32(float* d, const uint32_t* a, const uint32_t* b) {
    asm volatile(
        "mma.sync.aligned.m16n8k8.row.col.f32.tf32.tf32.f32 "
        "{%0,%1,%2,%3}, {%4,%5,%6,%7}, {%8,%9}, {%0,%1,%2,%3};"
        : "+f"(d[0]), "+f"(d[1]), "+f"(d[2]), "+f"(d[3])
        : "r"(a[0]), "r"(a[1]), "r"(a[2]), "r"(a[3]), "r"(b[0]), "r"(b[1]));
}

// =====================================================================
// GEMM via mma.sync tf32 (R13-certified math; R15-certified (256,2)).
// =====================================================================
#define BMM 128
#define BNN 128
#define BKK 32
#define ASTR 36
#define GT_BUF (2 * BMM * ASTR)
#define GT_SMEM (2 * GT_BUF * 4)

__global__ __launch_bounds__(256, 2)
void gemm_mma_kernel(const float* __restrict__ A, const float* __restrict__ Bw,
                     const float* __restrict__ bias, float* __restrict__ C,
                     int M, int Nn, int K)
{
    extern __shared__ float smg[];
    const int tid = threadIdx.x;
    const int lane = tid & 31, wid = tid >> 5;
    const int wr = wid >> 2, wc = wid & 3;
    const int gid = lane >> 2, tg = lane & 3;
    const int mBase = blockIdx.y * BMM;
    const int nBase = blockIdx.x * BNN;
    const int nTiles = K / BKK;

    float d[4][4][4];
#pragma unroll
    for (int mf = 0; mf < 4; ++mf)
#pragma unroll
        for (int nf = 0; nf < 4; ++nf)
#pragma unroll
            for (int e = 0; e < 4; ++e) d[mf][nf][e] = 0.f;

    auto load_tile = [&](int t, int buf) {
        const float* At = A + (size_t)mBase * K + t * BKK;
        const float* Bt = Bw + (size_t)nBase * K + t * BKK;
        float* as = smg + buf * GT_BUF;
        float* bs = as + BMM * ASTR;
#pragma unroll
        for (int e = 0; e < 8; ++e) {
            int idx = tid + e * 256;
            int r = (idx >> 3) & 127;
            int c = idx & 7;
            if (idx < 1024)
                cp_async16(&as[r * ASTR + c * 4], &At[(size_t)r * K + c * 4]);
            else
                cp_async16(&bs[r * ASTR + c * 4], &Bt[(size_t)r * K + c * 4]);
        }
        cp_commit();
    };

    load_tile(0, 0);
    cp_wait<0>();
    __syncthreads();

    for (int t = 0; t < nTiles; ++t) {
        int cur = t & 1;
        if (t + 1 < nTiles) load_tile(t + 1, cur ^ 1);

        const float* as = smg + cur * GT_BUF;
        const float* bs = as + BMM * ASTR;

#pragma unroll
        for (int ks = 0; ks < BKK / 8; ++ks) {
            int k0 = ks * 8;
            uint32_t af[4][4];
#pragma unroll
            for (int mf = 0; mf < 4; ++mf) {
                int mr = wr * 64 + mf * 16 + gid;
                af[mf][0] = f2tf32(as[mr * ASTR + k0 + tg]);
                af[mf][1] = f2tf32(as[(mr + 8) * ASTR + k0 + tg]);
                af[mf][2] = f2tf32(as[mr * ASTR + k0 + tg + 4]);
                af[mf][3] = f2tf32(as[(mr + 8) * ASTR + k0 + tg + 4]);
            }
            uint32_t bf[4][2];
#pragma unroll
            for (int nf = 0; nf < 4; ++nf) {
                int nc = wc * 32 + nf * 8 + gid;
                bf[nf][0] = f2tf32(bs[nc * ASTR + k0 + tg]);
                bf[nf][1] = f2tf32(bs[nc * ASTR + k0 + tg + 4]);
            }
#pragma unroll
            for (int mf = 0; mf < 4; ++mf)
#pragma unroll
                for (int nf = 0; nf < 4; ++nf)
                    mma_tf32(d[mf][nf], af[mf], bf[nf]);
        }

        if (t + 1 < nTiles) cp_wait<0>();
        __syncthreads();
    }

#pragma unroll
    for (int mf = 0; mf < 4; ++mf) {
#pragma unroll
        for (int nf = 0; nf < 4; ++nf) {
            int row = mBase + wr * 64 + mf * 16 + gid;
            int col = nBase + wc * 32 + nf * 8 + 2 * tg;
            float b0 = bias ? bias[col]     : 0.f;
            float b1 = bias ? bias[col + 1] : 0.f;
            float2 v0 = {d[mf][nf][0] + b0, d[mf][nf][1] + b1};
            float2 v1 = {d[mf][nf][2] + b0, d[mf][nf][3] + b1};
            *(float2*)&C[(size_t)row * Nn + col] = v0;
            *(float2*)&C[(size_t)(row + 8) * Nn + col] = v1;
        }
    }
}

// =====================================================================
// Warp-parallel rmsnorm + rope + split. Certified R8/R9 logic, plus
// tf32 RNA-rounding at the WRITE (bit-identical to attn5's downstream
// rounding; deletes the cvts from attn's hot loops).
// =====================================================================
__global__ void norm_rope_warp(const float* __restrict__ pos,
                               const float* __restrict__ qn_w,
                               const float* __restrict__ kn_w)
{
    int gw = (blockIdx.x * blockDim.x + threadIdx.x) >> 5;
    int t  = threadIdx.x & 31;
    if (gw >= BATCH * SEQ * NH) return;
    int h   = gw % NH;
    int tok = gw / NH;
    int b = tok / SEQ, n = tok % SEQ;

    const size_t base = (size_t)tok * (3 * DIM) + h * DH + 2 * t;
    float2 qv = *(const float2*)&g_qkv[base];
    float2 kv = *(const float2*)&g_qkv[base + DIM];
    float2 vv = *(const float2*)&g_qkv[base + 2 * DIM];

    float sq = qv.x * qv.x + qv.y * qv.y;
    float sk = kv.x * kv.x + kv.y * kv.y;
#pragma unroll
    for (int o = 16; o; o >>= 1) {
        sq += __shfl_xor_sync(0xffffffffu, sq, o);
        sk += __shfl_xor_sync(0xffffffffu, sk, o);
    }
    float rq = rsqrtf(sq * (1.0f / DH) + 1e-6f);
    float rk = rsqrtf(sk * (1.0f / DH) + 1e-6f);
    qv.x *= rq * qn_w[2 * t]; qv.y *= rq * qn_w[2 * t + 1];
    kv.x *= rk * kn_w[2 * t]; kv.y *= rk * kn_w[2 * t + 1];

    if (t < ROPE_DIM / 2) {
        int axis = t / HALF;
        int j = t - axis * HALF;
        float freq = powf(10000.0f, -(float)j / (float)HALF);
        float ang = pos[(size_t)tok * 3 + axis] * freq;
        float c = cosf(ang), s = sinf(ang);
        float qe = qv.x * c - qv.y * s, qo = qv.x * s + qv.y * c;
        qv.x = qe; qv.y = qo;
        float ke = kv.x * c - kv.y * s, ko = kv.x * s + kv.y * c;
        kv.x = ke; kv.y = ko;
    }

    // tf32 RNA pre-rounding (identity vs attn5's load-time rounding)
    qv.x = __uint_as_float(f2tf32(qv.x)); qv.y = __uint_as_float(f2tf32(qv.y));
    kv.x = __uint_as_float(f2tf32(kv.x)); kv.y = __uint_as_float(f2tf32(kv.y));
    vv.x = __uint_as_float(f2tf32(vv.x)); vv.y = __uint_as_float(f2tf32(vv.y));

    const size_t ob = ((size_t)(b * NH + h) * SEQ + n) * DH + 2 * t;
    *(float2*)&g_q[ob] = qv;
    *(float2*)&g_k[ob] = kv;
    *(float2*)&g_v[ob] = vv;
}

// =====================================================================
// Flash attention v5 (R14-certified, 680.9us config), minus redundant
// cvts: q/k/v arrive pre-rounded, loads are reinterprets.
// q-tile 128, k-tile 64. 8 warps 2x4. No-max softmax; P RNA-rounded
// before both row-sum and store. Pipeline: certified 2-sync scheme.
// =====================================================================
#define SST 68
#define A5_SMEM (512 * SST * 4)     // 139264 B
#define RPX 17

__global__ __launch_bounds__(256)
void attn5_kernel()
{
    extern __shared__ float sm[];
    float* Qs  = sm;                  // [128][SST] tf32 bits
    float* Ks0 = Qs  + 128 * SST;     // [64][SST]  tf32 bits (pre-rounded)
    float* Ks1 = Ks0 + 64 * SST;
    float* Vt0 = Ks1 + 64 * SST;      // [64][SST]  tf32 bits (V^T)
    float* Vt1 = Vt0 + 64 * SST;
    float* Ss  = Vt1 + 64 * SST;      // [128][SST] tf32 bits (P)

    const int tid = threadIdx.x;
    const int lane = tid & 31, wid = tid >> 5;
    const int wr = wid >> 2, wc = wid & 3;
    const int gid = lane >> 2, tg = lane & 3;
    const int bh = blockIdx.y;
    const int b  = bh / NH, h = bh % NH;
    const int n0 = blockIdx.x * 128;

    const float* Qg = g_q + ((size_t)bh * SEQ + n0) * DH;
    const float* Kg = g_k + (size_t)bh * SEQ * DH;
    const float* Vg = g_v + (size_t)bh * SEQ * DH;

    // ---- Q tile: copy (already tf32-rounded), natural [q][d] ----
#pragma unroll
    for (int e = 0; e < 32; ++e) {
        int idx = tid + e * 256;          // 0..8191
        int q = idx >> 6, dd = idx & 63;
        Qs[q * SST + dd] = Qg[(size_t)q * DH + dd];
    }

    auto load_k = [&](const float* src, float* dst) {
#pragma unroll
        for (int e = 0; e < 4; ++e) {
            int fidx = tid + e * 256;
            int r = fidx >> 4, c4 = (fidx & 15) * 4;
            cp_async16(&dst[r * SST + c4], &src[(size_t)r * DH + c4]);
        }
        cp_commit();
    };
    const int lrv = tid & 63;             // k row
    const int ldv = tid >> 6;             // d base 0..3

    // ---- preload tile 0 ----
    load_k(Kg, Ks0);
#pragma unroll
    for (int e = 0; e < 16; ++e)
        Vt0[(ldv + e * 4) * SST + lrv] = Vg[(size_t)lrv * DH + ldv + e * 4];
    cp_wait<0>();
    __syncthreads();     // (A) for kt=0

    float o[4][2][4];
    float lsA[4], lsB[4];
#pragma unroll
    for (int mf = 0; mf < 4; ++mf) {
        lsA[mf] = 0.f; lsB[mf] = 0.f;
#pragma unroll
        for (int nf = 0; nf < 2; ++nf)
#pragma unroll
            for (int e = 0; e < 4; ++e) o[mf][nf][e] = 0.f;
    }

    for (int kt = 0; kt < NT; ++kt) {
        float* Ksc = (kt & 1) ? Ks1 : Ks0;
        float* Vtc = (kt & 1) ? Vt1 : Vt0;
        float* Ksn = (kt & 1) ? Ks0 : Ks1;
        float* Vtn = (kt & 1) ? Vt0 : Vt1;

        // ---- prefetch next tile (safe: past sync A) ----
        float vreg[16];
        if (kt + 1 < NT) {
            const float* Kgn = Kg + (size_t)(kt + 1) * 64 * DH;
            const float* Vgn = Vg + (size_t)(kt + 1) * 64 * DH;
            load_k(Kgn, Ksn);
#pragma unroll
            for (int e = 0; e < 16; ++e)
                vreg[e] = Vgn[(size_t)lrv * DH + ldv + e * 4];
        }

        // ---- S = Q K^T (tf32 mma) ----
        float s[4][2][4];
#pragma unroll
        for (int mf = 0; mf < 4; ++mf)
#pragma unroll
            for (int nf = 0; nf < 2; ++nf)
#pragma unroll
                for (int e = 0; e < 4; ++e) s[mf][nf][e] = 0.f;

#pragma unroll
        for (int ds = 0; ds < 8; ++ds) {
            int d0 = ds * 8;
            uint32_t af[4][4];
#pragma unroll
            for (int mf = 0; mf < 4; ++mf) {
                int mr = wr * 64 + mf * 16 + gid;
                af[mf][0] = __float_as_uint(Qs[mr * SST + d0 + tg]);
                af[mf][1] = __float_as_uint(Qs[(mr + 8) * SST + d0 + tg]);
                af[mf][2] = __float_as_uint(Qs[mr * SST + d0 + tg + 4]);
                af[mf][3] = __float_as_uint(Qs[(mr + 8) * SST + d0 + tg + 4]);
            }
            uint32_t bf[2][2];
#pragma unroll
            for (int nf = 0; nf < 2; ++nf) {
                int kc = wc * 16 + nf * 8 + gid;
                bf[nf][0] = __float_as_uint(Ksc[kc * SST + d0 + tg]);
                bf[nf][1] = __float_as_uint(Ksc[kc * SST + d0 + tg + 4]);
            }
#pragma unroll
            for (int mf = 0; mf < 4; ++mf)
#pragma unroll
                for (int nf = 0; nf < 2; ++nf)
                    mma_tf32(s[mf][nf], af[mf], bf[nf]);
        }

        // ---- P = exp(S/8), RNA-round to tf32, sum rounded, store ----
#pragma unroll
        for (int mf = 0; mf < 4; ++mf) {
            int r0 = wr * 64 + mf * 16 + gid;
#pragma unroll
            for (int nf = 0; nf < 2; ++nf) {
                int col = wc * 16 + nf * 8 + 2 * tg;
                float p0 = __uint_as_float(f2tf32(__expf(s[mf][nf][0] * 0.125f)));
                float p1 = __uint_as_float(f2tf32(__expf(s[mf][nf][1] * 0.125f)));
                float p2 = __uint_as_float(f2tf32(__expf(s[mf][nf][2] * 0.125f)));
                float p3 = __uint_as_float(f2tf32(__expf(s[mf][nf][3] * 0.125f)));
                lsA[mf] += p0 + p1;
                lsB[mf] += p2 + p3;
                *(float2*)&Ss[r0 * SST + col] = make_float2(p0, p1);
                *(float2*)&Ss[(r0 + 8) * SST + col] = make_float2(p2, p3);
            }
        }
        __syncthreads();   // (B) P visible to all warps

        // ---- O += P V (tf32 mma; A=P from Ss, B=V^T from Vtc) ----
#pragma unroll
        for (int ks = 0; ks < 8; ++ks) {
            int kk0 = ks * 8;
            uint32_t af[4][4];
#pragma unroll
            for (int mf = 0; mf < 4; ++mf) {
                int mr = wr * 64 + mf * 16 + gid;
                af[mf][0] = __float_as_uint(Ss[mr * SST + kk0 + tg]);
                af[mf][1] = __float_as_uint(Ss[(mr + 8) * SST + kk0 + tg]);
                af[mf][2] = __float_as_uint(Ss[mr * SST + kk0 + tg + 4]);
                af[mf][3] = __float_as_uint(Ss[(mr + 8) * SST + kk0 + tg + 4]);
            }
            uint32_t bf[2][2];
#pragma unroll
            for (int nf = 0; nf < 2; ++nf) {
                int dc = wc * 16 + nf * 8 + gid;
                bf[nf][0] = __float_as_uint(Vtc[dc * SST + kk0 + tg]);
                bf[nf][1] = __float_as_uint(Vtc[dc * SST + kk0 + tg + 4]);
            }
#pragma unroll
            for (int mf = 0; mf < 4; ++mf)
#pragma unroll
                for (int nf = 0; nf < 2; ++nf)
                    mma_tf32(o[mf][nf], af[mf], bf[nf]);
        }

        // ---- stage next V^T -> other buffer (readers done pre-syncA) ----
        if (kt + 1 < NT) {
#pragma unroll
            for (int e = 0; e < 16; ++e)
                Vtn[(ldv + e * 4) * SST + lrv] = vreg[e];
        }

        cp_wait<0>();
        __syncthreads();   // (A) next buffers ready; Ss free
    }

    // ---- final row-sum reduction (reuse Ks0 as scratch [128][RPX]) ----
    float* red = Ks0;
#pragma unroll
    for (int mf = 0; mf < 4; ++mf) {
        int r0 = wr * 64 + mf * 16 + gid;
        red[r0 * RPX + wc * 4 + tg] = lsA[mf];
        red[(r0 + 8) * RPX + wc * 4 + tg] = lsB[mf];
    }
    __syncthreads();

#pragma unroll
    for (int mf = 0; mf < 4; ++mf) {
        int r0 = wr * 64 + mf * 16 + gid;
        float lA = 0.f, lB = 0.f;
#pragma unroll
        for (int t = 0; t < 16; ++t) {
            lA += red[r0 * RPX + t];
            lB += red[(r0 + 8) * RPX + t];
        }
        float invA = 1.0f / lA, invB = 1.0f / lB;
#pragma unroll
        for (int nf = 0; nf < 2; ++nf) {
            int dcol = wc * 16 + nf * 8 + 2 * tg;
            size_t offA = ((size_t)(b * SEQ + n0 + r0) * NH + h) * DH + dcol;
            size_t offB = ((size_t)(b * SEQ + n0 + r0 + 8) * NH + h) * DH + dcol;
            *(float2*)&g_att[offA] = make_float2(o[mf][nf][0] * invA,
                                                 o[mf][nf][1] * invA);
            *(float2*)&g_att[offB] = make_float2(o[mf][nf][2] * invB,
                                                 o[mf][nf][3] * invB);
        }
    }
}

// =====================================================================
// host launcher
// =====================================================================
extern "C" void kernel_launch(void* const* d_in, const int* in_sizes, int n_in,
                              void* d_out, int out_size)
{
    const float *x = 0, *pos = 0, *qkv_w = 0, *proj_w = 0, *proj_b = 0;
    const float *qn_w = 0, *kn_w = 0;
    for (int i = 0; i < n_in; ++i) {
        int s = in_sizes[i];
        const float* p = (const float*)d_in[i];
        if      (s == BATCH * SEQ * DIM)  x = p;
        else if (s == BATCH * SEQ * 3)    pos = p;
        else if (s == 3 * DIM * DIM)      qkv_w = p;
        else if (s == DIM * DIM)          proj_w = p;
        else if (s == DIM)                proj_b = p;
        else if (s == DH) { if (!qn_w) qn_w = p; else kn_w = p; }
    }
    float* out = (float*)d_out;

    float *qkv, *att;
    cudaGetSymbolAddress((void**)&qkv, g_qkv);
    cudaGetSymbolAddress((void**)&att, g_att);

    cudaFuncSetAttribute(gemm_mma_kernel, cudaFuncAttributeMaxDynamicSharedMemorySize,
                         GT_SMEM);
    cudaFuncSetAttribute(attn5_kernel, cudaFuncAttributeMaxDynamicSharedMemorySize,
                         A5_SMEM);

    // 1) qkv = x @ qkv_w^T  (tf32 mma.sync)
    gemm_mma_kernel<<<dim3(3 * DIM / BNN, BATCH * SEQ / BMM), 256, GT_SMEM>>>(
        x, qkv_w, nullptr, qkv, BATCH * SEQ, 3 * DIM, DIM);

    // 2) rmsnorm + rope + split (tf32 pre-rounded outputs)
    {
        int totalWarps = BATCH * SEQ * NH;
        int threads = 256;
        int blocks = (totalWarps * 32 + threads - 1) / threads;
        norm_rope_warp<<<blocks, threads>>>(pos, qn_w, kn_w);
    }

    // 3) flash attention v5 (tf32 mma.sync, q-tile 128 — R14 certified)
    attn5_kernel<<<dim3(SEQ / 128, BATCH * NH), 256, A5_SMEM>>>();

    // 4) out = att @ proj_w^T + proj_b  (tf32 mma.sync)
    gemm_mma_kernel<<<dim3(DIM / BNN, BATCH * SEQ / BMM), 256, GT_SMEM>>>(
        att, proj_w, proj_b, out, BATCH * SEQ, DIM, DIM);
}